// round 15
// baseline (speedup 1.0000x reference)
#include <cuda_runtime.h>
#include <cuda_bf16.h>
#include <cstdint>

#define BB 16384
#define TT 16
#define II 256
#define HH 128
#define GG 512
#define EPSF 1e-5f
#define NTH 256
#define NTS 256

// ---------------- scratch (device globals: allocation-free) ----------------
__device__ __align__(16) float g_a[(size_t)BB * TT * GG];   // LN_x(x@W_ih^T)*g_x + b_x + b
__device__ __align__(16) __nv_bfloat16 g_wih_hi[GG * II], g_wih_lo[GG * II];
__device__ __align__(16) __nv_bfloat16 g_whh_hi[GG * HH], g_whh_lo[GG * HH];

// ---------------- helpers ----------------
__device__ __forceinline__ uint32_t smem_u32(const void* p) {
    uint32_t a;
    asm("{ .reg .u64 t; cvta.to.shared.u64 t, %1; cvt.u32.u64 %0, t; }" : "=r"(a) : "l"(p));
    return a;
}
__device__ __forceinline__ void ldsm4(uint32_t* r, uint32_t a) {
    asm volatile("ldmatrix.sync.aligned.m8n8.x4.shared.b16 {%0,%1,%2,%3}, [%4];"
                 : "=r"(r[0]), "=r"(r[1]), "=r"(r[2]), "=r"(r[3]) : "r"(a));
}
__device__ __forceinline__ void mma16816(float* d, const uint32_t* a, uint32_t b0, uint32_t b1) {
    asm volatile(
        "mma.sync.aligned.m16n8k16.row.col.f32.bf16.bf16.f32 "
        "{%0,%1,%2,%3},{%4,%5,%6,%7},{%8,%9},{%0,%1,%2,%3};"
        : "+f"(d[0]), "+f"(d[1]), "+f"(d[2]), "+f"(d[3])
        : "r"(a[0]), "r"(a[1]), "r"(a[2]), "r"(a[3]), "r"(b0), "r"(b1));
}
#define CPA16(s, g) \
    asm volatile("cp.async.cg.shared.global [%0], [%1], 16;" \
                 :: "r"(s), "l"(__cvta_generic_to_global(g)) : "memory")
#define CP_COMMIT() asm volatile("cp.async.commit_group;" ::: "memory")
#define CP_WAIT0()  asm volatile("cp.async.wait_group 0;" ::: "memory")

__device__ __forceinline__ float qsum(float v) {
    v += __shfl_xor_sync(0xffffffffu, v, 1);
    v += __shfl_xor_sync(0xffffffffu, v, 2);
    return v;
}
__device__ __forceinline__ float sigm(float x) {
    return __fdividef(1.f, 1.f + __expf(-x));
}
__device__ __forceinline__ float tanh_fast(float x) {
    float xc = fminf(fmaxf(x, -9.f), 9.f);
    float e = __expf(2.f * xc);
    return __fdividef(e - 1.f, e + 1.f);
}
__device__ __forceinline__ uint32_t pack2(__nv_bfloat16 lo, __nv_bfloat16 hi) {
    return (uint32_t)__bfloat16_as_ushort(lo) | ((uint32_t)__bfloat16_as_ushort(hi) << 16);
}

// ---------------- smem layouts (bytes) ----------------
// proj v3: A hi/lo [128][264] resident; B chunk ring 2x[128][136] (34816 each)
#define PA_HI 0
#define PA_LO 67584
#define PB0   135168
#define PB1   169984
#define SMEM_PROJ 204800
// fused v3 (64 rows, 256 thr): A hi/lo [64][136]; B ring 2x(hi+lo) [128][136]; red 2KB
#define F_AHI 0
#define F_ALO 17408
#define F_B0  34816
#define F_B1  104448
#define F_RED 174080
#define SMEM_FUSED 176128

// ---------------- splitters ----------------
extern "C" __global__ void split_wih(const float* __restrict__ s) {
    int i = blockIdx.x * blockDim.x + threadIdx.x;
    if (i < GG * II) {
        float v = s[i];
        __nv_bfloat16 h = __float2bfloat16(v);
        g_wih_hi[i] = h;
        g_wih_lo[i] = __float2bfloat16(v - __bfloat162float(h));
    }
}
extern "C" __global__ void split_whh(const float* __restrict__ s) {
    int i = blockIdx.x * blockDim.x + threadIdx.x;
    if (i < GG * HH) {
        float v = s[i];
        __nv_bfloat16 h = __float2bfloat16(v);
        g_whh_hi[i] = h;
        g_whh_lo[i] = __float2bfloat16(v - __bfloat162float(h));
    }
}

// ---------------- proj v3: chunked cp.async B ring (16 chunks) ----------------
// chunk ci = (gq<<2) | (kh<<1) | part ; B chunk = W_ih[gq*128..+127][kh*128..+127]
__device__ __forceinline__ void issue_chunk(uint32_t sb, int tid, int ci) {
    const int gq = ci >> 2, kh = (ci >> 1) & 1, part = ci & 1;
    const __nv_bfloat16* src = (part ? g_wih_lo : g_wih_hi);
    const uint32_t slot = sb + ((ci & 1) ? PB1 : PB0);
#pragma unroll
    for (int it = 0; it < 8; ++it) {
        int c = tid + it * NTH;                 // 2048 transfers of 16B
        int n = c >> 4, k8 = (c & 15) * 8;
        CPA16(slot + n * 272 + k8 * 2,
              src + (size_t)(gq * HH + n) * II + kh * HH + k8);
    }
    CP_COMMIT();
}

extern "C" __global__ void __launch_bounds__(NTH, 1)
proj_kernel(const float* __restrict__ x, const float* __restrict__ bias,
            const float* __restrict__ gx, const float* __restrict__ bx)
{
    extern __shared__ char smc[];
    const uint32_t sb = smem_u32(smc);
    const int tid = threadIdx.x, lane = tid & 31, wid = tid >> 5;
    const int m0 = blockIdx.x * 128;
    const int wr0 = wid * 16;

    issue_chunk(sb, tid, 0);                    // chunk 0 flies during A-stage

    // stage A: x fp32 -> bf16 hi/lo, K=256 resident (row stride 528 B)
#pragma unroll
    for (int it = 0; it < 16; ++it) {
        int c = tid + it * NTH;
        int row = c >> 5, k8 = (c & 31) * 8;
        const float* src = x + (size_t)(m0 + row) * II + k8;
        float4 v0 = *(const float4*)src, v1 = *(const float4*)(src + 4);
        __nv_bfloat16 h0 = __float2bfloat16(v0.x), h1 = __float2bfloat16(v0.y);
        __nv_bfloat16 h2 = __float2bfloat16(v0.z), h3 = __float2bfloat16(v0.w);
        __nv_bfloat16 h4 = __float2bfloat16(v1.x), h5 = __float2bfloat16(v1.y);
        __nv_bfloat16 h6 = __float2bfloat16(v1.z), h7 = __float2bfloat16(v1.w);
        uint4 hp, lp;
        hp.x = pack2(h0, h1); hp.y = pack2(h2, h3);
        hp.z = pack2(h4, h5); hp.w = pack2(h6, h7);
        lp.x = pack2(__float2bfloat16(v0.x - __bfloat162float(h0)),
                     __float2bfloat16(v0.y - __bfloat162float(h1)));
        lp.y = pack2(__float2bfloat16(v0.z - __bfloat162float(h2)),
                     __float2bfloat16(v0.w - __bfloat162float(h3)));
        lp.z = pack2(__float2bfloat16(v1.x - __bfloat162float(h4)),
                     __float2bfloat16(v1.y - __bfloat162float(h5)));
        lp.w = pack2(__float2bfloat16(v1.z - __bfloat162float(h6)),
                     __float2bfloat16(v1.w - __bfloat162float(h7)));
        *(uint4*)(smc + PA_HI + row * 528 + k8 * 2) = hp;
        *(uint4*)(smc + PA_LO + row * 528 + k8 * 2) = lp;
    }

    const int rA = wr0 + (lane >> 2);
    const size_t mA = (size_t)m0 + rA, mB = mA + 8;

    float acc[16][4];
#pragma unroll 1
    for (int ci = 0; ci < 16; ++ci) {
        const int kh = (ci >> 1) & 1, part = ci & 1;
        if ((ci & 3) == 0) {
#pragma unroll
            for (int j = 0; j < 16; ++j)
                acc[j][0] = acc[j][1] = acc[j][2] = acc[j][3] = 0.f;
        }
        CP_WAIT0();
        __syncthreads();                        // chunk ci visible; slot ci^1 free
        if (ci < 15) issue_chunk(sb, tid, ci + 1);

        const uint32_t abase = sb + PA_HI + (wr0 + (lane & 15)) * 528 + kh * 256 + ((lane >> 4) << 4);
        const uint32_t bb0 = sb + ((ci & 1) ? PB1 : PB0)
                           + ((lane & 7) + ((lane >> 4) << 3)) * 272 + (((lane >> 3) & 1) << 4);
        if (part == 0) {                        // hi chunk: ah*bh + al*bh
#pragma unroll
            for (int ks = 0; ks < 8; ++ks) {
                uint32_t ah[4], al[4];
                ldsm4(ah, abase + ks * 32);
                ldsm4(al, abase + ks * 32 + (PA_LO - PA_HI));
#pragma unroll
                for (int g = 0; g < 8; ++g) {
                    uint32_t b4[4];
                    ldsm4(b4, bb0 + g * 16 * 272 + ks * 32);
                    mma16816(acc[2 * g],     ah, b4[0], b4[1]);
                    mma16816(acc[2 * g + 1], ah, b4[2], b4[3]);
                    mma16816(acc[2 * g],     al, b4[0], b4[1]);
                    mma16816(acc[2 * g + 1], al, b4[2], b4[3]);
                }
            }
        } else {                                // lo chunk: ah*bl
#pragma unroll
            for (int ks = 0; ks < 8; ++ks) {
                uint32_t ah[4];
                ldsm4(ah, abase + ks * 32);
#pragma unroll
                for (int g = 0; g < 8; ++g) {
                    uint32_t b4[4];
                    ldsm4(b4, bb0 + g * 16 * 272 + ks * 32);
                    mma16816(acc[2 * g],     ah, b4[0], b4[1]);
                    mma16816(acc[2 * g + 1], ah, b4[2], b4[3]);
                }
            }
        }

        if ((ci & 3) == 3) {                    // gate gq = ci>>2 complete
            const int egq = ci >> 2;
            float s0 = 0.f, q0 = 0.f, s1 = 0.f, q1 = 0.f;
#pragma unroll
            for (int j = 0; j < 16; ++j) {
                s0 += acc[j][0] + acc[j][1]; q0 += acc[j][0] * acc[j][0] + acc[j][1] * acc[j][1];
                s1 += acc[j][2] + acc[j][3]; q1 += acc[j][2] * acc[j][2] + acc[j][3] * acc[j][3];
            }
            s0 = qsum(s0); q0 = qsum(q0); s1 = qsum(s1); q1 = qsum(q1);
            const float mu0 = s0 * (1.f / HH), rs0 = rsqrtf(q0 * (1.f / HH) - mu0 * mu0 + EPSF);
            const float mu1 = s1 * (1.f / HH), rs1 = rsqrtf(q1 * (1.f / HH) - mu1 * mu1 + EPSF);
#pragma unroll
            for (int j = 0; j < 16; ++j)
#pragma unroll
                for (int e = 0; e < 4; ++e) {
                    int col = 8 * j + 2 * (lane & 3) + (e & 1);
                    int gcol = egq * HH + col;
                    float mu = (e < 2) ? mu0 : mu1, rs = (e < 2) ? rs0 : rs1;
                    size_t m = (e < 2) ? mA : mB;
                    g_a[m * GG + gcol] = (acc[j][e] - mu) * rs * gx[gcol] + bx[gcol] + bias[gcol];
                }
        }
    }
}

// ---------------- fused v3 (R13-passing version, unchanged) ----------------
__device__ __forceinline__ void issue_whh(uint32_t sb, int tid, int gq, int buf) {
    const uint32_t base = sb + (buf ? F_B1 : F_B0);
#pragma unroll
    for (int it = 0; it < 16; ++it) {
        int c = tid + it * NTS;                 // 4096 transfers: hi then lo
        int part = c >> 11, cc = c & 2047;
        int n = cc >> 4, k8 = (cc & 15) * 8;
        const __nv_bfloat16* src = (part ? g_whh_lo : g_whh_hi) + (size_t)(gq * HH + n) * HH + k8;
        CPA16(base + part * 34816 + n * 272 + k8 * 2, src);
    }
    CP_COMMIT();
}

extern "C" __global__ void __launch_bounds__(NTS, 1)
fused_kernel(const float* __restrict__ gh, const float* __restrict__ bh,
             const float* __restrict__ gc, const float* __restrict__ bc,
             const float* __restrict__ h0, const float* __restrict__ c0,
             float* __restrict__ out, int write_hn)
{
    extern __shared__ char smc[];
    const uint32_t sb = smem_u32(smc);
    const int tid = threadIdx.x, lane = tid & 31, wid = tid >> 5;
    const int m0 = blockIdx.x * 64;
    const int wr0 = (wid >> 1) * 16;
    const int half = wid & 1, cb = half * 64;

    issue_whh(sb, tid, 0, 0);                   // B for (t=0, gate i) -> buf 0

#pragma unroll
    for (int it = 0; it < 8; ++it) {
        int c = tid + it * NTS;
        int row = c >> 5, c4 = (c & 31) * 4;
        float4 v = *(const float4*)(h0 + (size_t)(m0 + row) * HH + c4);
        __nv_bfloat16 b0 = __float2bfloat16(v.x), b1 = __float2bfloat16(v.y);
        __nv_bfloat16 b2 = __float2bfloat16(v.z), b3 = __float2bfloat16(v.w);
        uint2 hp, lp;
        hp.x = pack2(b0, b1); hp.y = pack2(b2, b3);
        lp.x = pack2(__float2bfloat16(v.x - __bfloat162float(b0)),
                     __float2bfloat16(v.y - __bfloat162float(b1)));
        lp.y = pack2(__float2bfloat16(v.z - __bfloat162float(b2)),
                     __float2bfloat16(v.w - __bfloat162float(b3)));
        *(uint2*)(smc + F_AHI + row * 272 + c4 * 2) = hp;
        *(uint2*)(smc + F_ALO + row * 272 + c4 * 2) = lp;
    }

    const int rA = wr0 + (lane >> 2), rB = rA + 8;
    const size_t bidxA = (size_t)m0 + rA, bidxB = bidxA + 8;
    const int q2 = 2 * (lane & 3);

    float C[8][4];
#pragma unroll
    for (int j = 0; j < 8; ++j) {
        float2 va = *(const float2*)(c0 + bidxA * HH + cb + 8 * j + q2);
        float2 vb = *(const float2*)(c0 + bidxB * HH + cb + 8 * j + q2);
        C[j][0] = va.x; C[j][1] = va.y; C[j][2] = vb.x; C[j][3] = vb.y;
    }

    const uint32_t abase = sb + F_AHI + (wr0 + (lane & 15)) * 272 + ((lane >> 4) << 4);
    const uint32_t bfo = ((cb + (lane & 7) + ((lane >> 4) << 3)) * 272 + (((lane >> 3) & 1) << 4));

    float accA[8][4], accB[8][4], S[8][4];
    float2 apA[8], apB[8];
    float sc0, qc0, sc1, qc1;

    auto mma_phase = [&](float (&ACC)[8][4], int buf) {
        const uint32_t bb = sb + (buf ? F_B1 : F_B0) + bfo;
#pragma unroll
        for (int j = 0; j < 8; ++j) { ACC[j][0] = ACC[j][1] = ACC[j][2] = ACC[j][3] = 0.f; }
#pragma unroll
        for (int ks = 0; ks < 8; ++ks) {
            uint32_t ah[4], al[4];
            ldsm4(ah, abase + ks * 32);
            ldsm4(al, abase + ks * 32 + (F_ALO - F_AHI));
#pragma unroll
            for (int g = 0; g < 4; ++g) {
                uint32_t bh4[4], bl4[4];
                uint32_t ba = bb + g * 16 * 272 + ks * 32;
                ldsm4(bh4, ba);
                ldsm4(bl4, ba + 34816);
                mma16816(ACC[2 * g],     ah, bh4[0], bh4[1]);
                mma16816(ACC[2 * g + 1], ah, bh4[2], bh4[3]);
                mma16816(ACC[2 * g],     al, bh4[0], bh4[1]);
                mma16816(ACC[2 * g + 1], al, bh4[2], bh4[3]);
                mma16816(ACC[2 * g],     ah, bl4[0], bl4[1]);
                mma16816(ACC[2 * g + 1], ah, bl4[2], bl4[3]);
            }
        }
    };

    auto load_ap = [&](int t, int gq) {
        const float* aA = g_a + ((size_t)bidxA * TT + t) * GG + gq * HH + cb;
        const float* aB = g_a + ((size_t)bidxB * TT + t) * GG + gq * HH + cb;
#pragma unroll
        for (int j = 0; j < 8; ++j) {
            apA[j] = *(const float2*)(aA + 8 * j + q2);
            apB[j] = *(const float2*)(aB + 8 * j + q2);
        }
    };

    auto gate_ln = [&](float (&ACC)[8][4], int reg,
                       float& mu0, float& rs0, float& mu1, float& rs1) {
        float2* red = (float2*)(smc + F_RED + reg * 1024);
        float s0 = 0.f, q0 = 0.f, s1 = 0.f, q1 = 0.f;
#pragma unroll
        for (int j = 0; j < 8; ++j) {
            s0 += ACC[j][0] + ACC[j][1]; q0 += ACC[j][0] * ACC[j][0] + ACC[j][1] * ACC[j][1];
            s1 += ACC[j][2] + ACC[j][3]; q1 += ACC[j][2] * ACC[j][2] + ACC[j][3] * ACC[j][3];
        }
        s0 = qsum(s0); q0 = qsum(q0); s1 = qsum(s1); q1 = qsum(q1);
        if ((lane & 3) == 0) {
            red[rA * 2 + half] = make_float2(s0, q0);
            red[rB * 2 + half] = make_float2(s1, q1);
        }
        __syncthreads();
        float2 o0 = red[rA * 2 + (1 - half)], o1 = red[rB * 2 + (1 - half)];
        s0 += o0.x; q0 += o0.y; s1 += o1.x; q1 += o1.y;
        mu0 = s0 * (1.f / HH); rs0 = rsqrtf(q0 * (1.f / HH) - mu0 * mu0 + EPSF);
        mu1 = s1 * (1.f / HH); rs1 = rsqrtf(q1 * (1.f / HH) - mu1 * mu1 + EPSF);
    };

    auto epi = [&](float (&ACC)[8][4], int gq, int reg, int mode) {
        float mu0, rs0, mu1, rs1;
        gate_ln(ACC, reg, mu0, rs0, mu1, rs1);
#pragma unroll
        for (int j = 0; j < 8; ++j) {
            int colb = cb + 8 * j + q2;
            float2 gh2 = *(const float2*)(gh + gq * HH + colb);
            float2 bh2 = *(const float2*)(bh + gq * HH + colb);
            float ar[4] = {apA[j].x, apA[j].y, apB[j].x, apB[j].y};
#pragma unroll
            for (int e = 0; e < 4; ++e) {
                float mu = (e < 2) ? mu0 : mu1, rs = (e < 2) ? rs0 : rs1;
                float gv = (e & 1) ? gh2.y : gh2.x;
                float bv = (e & 1) ? bh2.y : bh2.x;
                float gn = (ACC[j][e] - mu) * rs * gv + bv + ar[e];
                if (mode == 0) {
                    S[j][e] = sigm(gn);
                } else if (mode == 1) {
                    S[j][e] *= tanh_fast(gn);
                } else if (mode == 2) {
                    float cv = sigm(gn) * C[j][e] + S[j][e];
                    C[j][e] = cv;
                    if (e < 2) { sc0 += cv; qc0 += cv * cv; }
                    else       { sc1 += cv; qc1 += cv * cv; }
                } else {
                    ACC[j][e] = sigm(gn);
                }
            }
        }
    };

#pragma unroll 1
    for (int t = 0; t < TT; ++t) {
        sc0 = 0.f; qc0 = 0.f; sc1 = 0.f; qc1 = 0.f;

        CP_WAIT0(); __syncthreads();
        issue_whh(sb, tid, 2, (t * 4 + 1) & 1);
        mma_phase(accA, (t * 4) & 1);
        load_ap(t, 0);

        CP_WAIT0(); __syncthreads();
        issue_whh(sb, tid, 1, (t * 4 + 2) & 1);
        mma_phase(accB, (t * 4 + 1) & 1);
        epi(accA, 0, 0, 0);
        load_ap(t, 2);

        CP_WAIT0(); __syncthreads();
        issue_whh(sb, tid, 3, (t * 4 + 3) & 1);
        mma_phase(accA, (t * 4 + 2) & 1);
        epi(accB, 2, 1, 1);
        load_ap(t, 1);

        CP_WAIT0(); __syncthreads();
        if (t + 1 < TT) issue_whh(sb, tid, 0, (t * 4 + 4) & 1);
        mma_phase(accB, (t * 4 + 3) & 1);
        epi(accA, 1, 0, 2);
        load_ap(t, 3);

        epi(accB, 3, 1, 3);

        {
            float2* red = (float2*)(smc + F_RED);
            float s0 = qsum(sc0), q0 = qsum(qc0), s1 = qsum(sc1), q1 = qsum(qc1);
            if ((lane & 3) == 0) {
                red[rA * 2 + half] = make_float2(s0, q0);
                red[rB * 2 + half] = make_float2(s1, q1);
            }
            __syncthreads();
            float2 o0 = red[rA * 2 + (1 - half)], o1 = red[rB * 2 + (1 - half)];
            s0 += o0.x; q0 += o0.y; s1 += o1.x; q1 += o1.y;
            const float mc0 = s0 * (1.f / HH), rc0 = rsqrtf(q0 * (1.f / HH) - mc0 * mc0 + EPSF);
            const float mc1 = s1 * (1.f / HH), rc1 = rsqrtf(q1 * (1.f / HH) - mc1 * mc1 + EPSF);

            float* oA = out + (bidxA * TT + t) * HH;
            float* oB = out + (bidxB * TT + t) * HH;
#pragma unroll
            for (int j = 0; j < 8; ++j) {
                int colb = cb + 8 * j + q2;
                float2 gc2 = *(const float2*)(gc + colb);
                float2 bc2 = *(const float2*)(bc + colb);
                float hv[4];
#pragma unroll
                for (int e = 0; e < 4; ++e) {
                    float mc = (e < 2) ? mc0 : mc1, rc = (e < 2) ? rc0 : rc1;
                    float gv = (e & 1) ? gc2.y : gc2.x;
                    float bv = (e & 1) ? bc2.y : bc2.x;
                    float cl = (C[j][e] - mc) * rc * gv + bv;
                    hv[e] = accB[j][e] * tanh_fast(cl);
                }
                *(float2*)(oA + colb) = make_float2(hv[0], hv[1]);
                *(float2*)(oB + colb) = make_float2(hv[2], hv[3]);
                if (write_hn && t == TT - 1) {
                    *(float2*)(out + (size_t)BB * TT * HH + bidxA * HH + colb) = make_float2(hv[0], hv[1]);
                    *(float2*)(out + (size_t)BB * TT * HH + bidxB * HH + colb) = make_float2(hv[2], hv[3]);
                }
                __nv_bfloat16 b0 = __float2bfloat16(hv[0]), b1 = __float2bfloat16(hv[1]);
                __nv_bfloat16 b2 = __float2bfloat16(hv[2]), b3 = __float2bfloat16(hv[3]);
                *(uint32_t*)(smc + F_AHI + rA * 272 + colb * 2) = pack2(b0, b1);
                *(uint32_t*)(smc + F_AHI + rB * 272 + colb * 2) = pack2(b2, b3);
                *(uint32_t*)(smc + F_ALO + rA * 272 + colb * 2) =
                    pack2(__float2bfloat16(hv[0] - __bfloat162float(b0)),
                          __float2bfloat16(hv[1] - __bfloat162float(b1)));
                *(uint32_t*)(smc + F_ALO + rB * 272 + colb * 2) =
                    pack2(__float2bfloat16(hv[2] - __bfloat162float(b2)),
                          __float2bfloat16(hv[3] - __bfloat162float(b3)));
            }
        }
    }
}

// ---------------- host ----------------
extern "C" void kernel_launch(void* const* d_in, const int* in_sizes, int n_in,
                              void* d_out, int out_size)
{
    const float* x    = (const float*)d_in[0];
    const float* h0   = (const float*)d_in[1];
    const float* c0   = (const float*)d_in[2];
    const float* W_ih = (const float*)d_in[3];
    const float* W_hh = (const float*)d_in[4];
    const float* bias = (const float*)d_in[5];
    const float* g_x  = (const float*)d_in[6];
    const float* b_x  = (const float*)d_in[7];
    const float* gh   = (const float*)d_in[8];
    const float* bh   = (const float*)d_in[9];
    const float* gc   = (const float*)d_in[10];
    const float* bc   = (const float*)d_in[11];
    float* out = (float*)d_out;

    cudaFuncSetAttribute(proj_kernel,  cudaFuncAttributeMaxDynamicSharedMemorySize, SMEM_PROJ);
    cudaFuncSetAttribute(fused_kernel, cudaFuncAttributeMaxDynamicSharedMemorySize, SMEM_FUSED);

    split_wih<<<(GG * II + 255) / 256, 256>>>(W_ih);
    split_whh<<<(GG * HH + 255) / 256, 256>>>(W_hh);

    proj_kernel<<<(BB * TT) / 128, NTH, SMEM_PROJ>>>(x, bias, g_x, b_x);

    const long long need = (long long)BB * TT * HH + (long long)BB * HH;
    const int write_full = (out_size >= need) ? 1 : 0;

    fused_kernel<<<BB / 64, NTS, SMEM_FUSED>>>(gh, bh, gc, bc, h0, c0, out, write_full);
}

// round 16
// speedup vs baseline: 1.0200x; 1.0200x over previous
#include <cuda_runtime.h>
#include <cuda_bf16.h>
#include <cstdint>

#define BB 16384
#define TT 16
#define II 256
#define HH 128
#define GG 512
#define EPSF 1e-5f
#define NTH 256
#define NTS 256

// ---------------- scratch (device globals: allocation-free) ----------------
__device__ __align__(16) float g_a[(size_t)BB * TT * GG];   // LN_x(x@W_ih^T)*g_x + b_x + b
__device__ __align__(16) __nv_bfloat16 g_wih_hi[GG * II], g_wih_lo[GG * II];
__device__ __align__(16) __nv_bfloat16 g_whh_hi[GG * HH], g_whh_lo[GG * HH];

// ---------------- helpers ----------------
__device__ __forceinline__ uint32_t smem_u32(const void* p) {
    uint32_t a;
    asm("{ .reg .u64 t; cvta.to.shared.u64 t, %1; cvt.u32.u64 %0, t; }" : "=r"(a) : "l"(p));
    return a;
}
__device__ __forceinline__ void ldsm4(uint32_t* r, uint32_t a) {
    asm volatile("ldmatrix.sync.aligned.m8n8.x4.shared.b16 {%0,%1,%2,%3}, [%4];"
                 : "=r"(r[0]), "=r"(r[1]), "=r"(r[2]), "=r"(r[3]) : "r"(a));
}
__device__ __forceinline__ void mma16816(float* d, const uint32_t* a, uint32_t b0, uint32_t b1) {
    asm volatile(
        "mma.sync.aligned.m16n8k16.row.col.f32.bf16.bf16.f32 "
        "{%0,%1,%2,%3},{%4,%5,%6,%7},{%8,%9},{%0,%1,%2,%3};"
        : "+f"(d[0]), "+f"(d[1]), "+f"(d[2]), "+f"(d[3])
        : "r"(a[0]), "r"(a[1]), "r"(a[2]), "r"(a[3]), "r"(b0), "r"(b1));
}
#define CPA16(s, g) \
    asm volatile("cp.async.cg.shared.global [%0], [%1], 16;" \
                 :: "r"(s), "l"(__cvta_generic_to_global(g)) : "memory")
#define CP_COMMIT() asm volatile("cp.async.commit_group;" ::: "memory")
#define CP_WAIT0()  asm volatile("cp.async.wait_group 0;" ::: "memory")

__device__ __forceinline__ float qsum(float v) {
    v += __shfl_xor_sync(0xffffffffu, v, 1);
    v += __shfl_xor_sync(0xffffffffu, v, 2);
    return v;
}
__device__ __forceinline__ float sigm(float x) {
    return __fdividef(1.f, 1.f + __expf(-x));
}
__device__ __forceinline__ float tanh_fast(float x) {
    float xc = fminf(fmaxf(x, -9.f), 9.f);
    float e = __expf(2.f * xc);
    return __fdividef(e - 1.f, e + 1.f);
}
__device__ __forceinline__ uint32_t pack2(__nv_bfloat16 lo, __nv_bfloat16 hi) {
    return (uint32_t)__bfloat16_as_ushort(lo) | ((uint32_t)__bfloat16_as_ushort(hi) << 16);
}

// ---------------- smem layouts (bytes) ----------------
// proj v4 (64 rows, 2 CTA/SM): A hi/lo [64][264]; B chunk ring 2x[128][72bf16=144B]; red 1KB
#define PA_HI 0
#define PA_LO 33792
#define PB0   67584
#define PB1   86016
#define P_RED 104448
#define SMEM_PROJ 105472
// fused v3 (64 rows, 256 thr): A hi/lo [64][136]; B ring 2x(hi+lo) [128][136]; red 2KB
#define F_AHI 0
#define F_ALO 17408
#define F_B0  34816
#define F_B1  104448
#define F_RED 174080
#define SMEM_FUSED 176128

// ---------------- splitters ----------------
extern "C" __global__ void split_wih(const float* __restrict__ s) {
    int i = blockIdx.x * blockDim.x + threadIdx.x;
    if (i < GG * II) {
        float v = s[i];
        __nv_bfloat16 h = __float2bfloat16(v);
        g_wih_hi[i] = h;
        g_wih_lo[i] = __float2bfloat16(v - __bfloat162float(h));
    }
}
extern "C" __global__ void split_whh(const float* __restrict__ s) {
    int i = blockIdx.x * blockDim.x + threadIdx.x;
    if (i < GG * HH) {
        float v = s[i];
        __nv_bfloat16 h = __float2bfloat16(v);
        g_whh_hi[i] = h;
        g_whh_lo[i] = __float2bfloat16(v - __bfloat162float(h));
    }
}

// ---------------- proj v4: 64-row CTAs, 2/SM, chunked K=64 B ring ----------------
// chunk ci = (gq<<3) | (kh<<1) | part ; chunk = W_ih[gq*128..+127][kh*64..+63] hi/lo
__device__ __forceinline__ void issue_chunk(uint32_t sb, int tid, int ci) {
    const int gq = ci >> 3, kh = (ci >> 1) & 3, part = ci & 1;
    const __nv_bfloat16* src = (part ? g_wih_lo : g_wih_hi);
    const uint32_t slot = sb + ((ci & 1) ? PB1 : PB0);
#pragma unroll
    for (int it = 0; it < 4; ++it) {
        int c = tid + it * NTH;                 // 1024 transfers of 16B
        int n = c >> 3, k8 = (c & 7) * 8;
        CPA16(slot + n * 144 + k8 * 2,
              src + (size_t)(gq * HH + n) * II + kh * 64 + k8);
    }
    CP_COMMIT();
}

extern "C" __global__ void __launch_bounds__(NTH, 2)
proj_kernel(const float* __restrict__ x, const float* __restrict__ bias,
            const float* __restrict__ gx, const float* __restrict__ bx)
{
    extern __shared__ char smc[];
    const uint32_t sb = smem_u32(smc);
    const int tid = threadIdx.x, lane = tid & 31, wid = tid >> 5;
    const int m0 = blockIdx.x * 64;
    const int wr0 = (wid >> 1) * 16;
    const int half = wid & 1, cb = half * 64;
    float2* red = (float2*)(smc + P_RED);

    issue_chunk(sb, tid, 0);                    // chunk 0 flies during A-stage

    // stage A: x fp32 -> bf16 hi/lo, 64 rows, K=256 resident (row stride 528 B)
#pragma unroll
    for (int it = 0; it < 8; ++it) {
        int c = tid + it * NTH;
        int row = c >> 5, k8 = (c & 31) * 8;
        const float* src = x + (size_t)(m0 + row) * II + k8;
        float4 v0 = *(const float4*)src, v1 = *(const float4*)(src + 4);
        __nv_bfloat16 h0 = __float2bfloat16(v0.x), h1 = __float2bfloat16(v0.y);
        __nv_bfloat16 h2 = __float2bfloat16(v0.z), h3 = __float2bfloat16(v0.w);
        __nv_bfloat16 h4 = __float2bfloat16(v1.x), h5 = __float2bfloat16(v1.y);
        __nv_bfloat16 h6 = __float2bfloat16(v1.z), h7 = __float2bfloat16(v1.w);
        uint4 hp, lp;
        hp.x = pack2(h0, h1); hp.y = pack2(h2, h3);
        hp.z = pack2(h4, h5); hp.w = pack2(h6, h7);
        lp.x = pack2(__float2bfloat16(v0.x - __bfloat162float(h0)),
                     __float2bfloat16(v0.y - __bfloat162float(h1)));
        lp.y = pack2(__float2bfloat16(v0.z - __bfloat162float(h2)),
                     __float2bfloat16(v0.w - __bfloat162float(h3)));
        lp.z = pack2(__float2bfloat16(v1.x - __bfloat162float(h4)),
                     __float2bfloat16(v1.y - __bfloat162float(h5)));
        lp.w = pack2(__float2bfloat16(v1.z - __bfloat162float(h6)),
                     __float2bfloat16(v1.w - __bfloat162float(h7)));
        *(uint4*)(smc + PA_HI + row * 528 + k8 * 2) = hp;
        *(uint4*)(smc + PA_LO + row * 528 + k8 * 2) = lp;
    }

    const int rA = wr0 + (lane >> 2), rB = rA + 8;
    const size_t mA = (size_t)m0 + rA, mB = mA + 8;
    const int q2 = 2 * (lane & 3);

    float acc[8][4];
#pragma unroll 1
    for (int ci = 0; ci < 32; ++ci) {
        const int kh = (ci >> 1) & 3, part = ci & 1;
        if ((ci & 7) == 0) {
#pragma unroll
            for (int j = 0; j < 8; ++j)
                acc[j][0] = acc[j][1] = acc[j][2] = acc[j][3] = 0.f;
        }
        CP_WAIT0();
        __syncthreads();                        // chunk ci visible; slot ci^1 free
        if (ci < 31) issue_chunk(sb, tid, ci + 1);

        const uint32_t abase = sb + PA_HI + (wr0 + (lane & 15)) * 528 + kh * 128 + ((lane >> 4) << 4);
        const uint32_t bb0 = sb + ((ci & 1) ? PB1 : PB0)
                           + (cb + (lane & 7) + ((lane >> 4) << 3)) * 144 + (((lane >> 3) & 1) << 4);
        if (part == 0) {                        // hi chunk: ah*bh + al*bh
#pragma unroll
            for (int ks = 0; ks < 4; ++ks) {
                uint32_t ah[4], al[4];
                ldsm4(ah, abase + ks * 32);
                ldsm4(al, abase + ks * 32 + (PA_LO - PA_HI));
#pragma unroll
                for (int g = 0; g < 4; ++g) {
                    uint32_t b4[4];
                    ldsm4(b4, bb0 + g * 16 * 144 + ks * 32);
                    mma16816(acc[2 * g],     ah, b4[0], b4[1]);
                    mma16816(acc[2 * g + 1], ah, b4[2], b4[3]);
                    mma16816(acc[2 * g],     al, b4[0], b4[1]);
                    mma16816(acc[2 * g + 1], al, b4[2], b4[3]);
                }
            }
        } else {                                // lo chunk: ah*bl
#pragma unroll
            for (int ks = 0; ks < 4; ++ks) {
                uint32_t ah[4];
                ldsm4(ah, abase + ks * 32);
#pragma unroll
                for (int g = 0; g < 4; ++g) {
                    uint32_t b4[4];
                    ldsm4(b4, bb0 + g * 16 * 144 + ks * 32);
                    mma16816(acc[2 * g],     ah, b4[0], b4[1]);
                    mma16816(acc[2 * g + 1], ah, b4[2], b4[3]);
                }
            }
        }

        if ((ci & 7) == 7) {                    // gate gq = ci>>3 complete
            const int egq = ci >> 3;
            float s0 = 0.f, q0 = 0.f, s1 = 0.f, q1 = 0.f;
#pragma unroll
            for (int j = 0; j < 8; ++j) {
                s0 += acc[j][0] + acc[j][1]; q0 += acc[j][0] * acc[j][0] + acc[j][1] * acc[j][1];
                s1 += acc[j][2] + acc[j][3]; q1 += acc[j][2] * acc[j][2] + acc[j][3] * acc[j][3];
            }
            s0 = qsum(s0); q0 = qsum(q0); s1 = qsum(s1); q1 = qsum(q1);
            if ((lane & 3) == 0) {
                red[rA * 2 + half] = make_float2(s0, q0);
                red[rB * 2 + half] = make_float2(s1, q1);
            }
            __syncthreads();
            {
                float2 o0 = red[rA * 2 + (1 - half)], o1 = red[rB * 2 + (1 - half)];
                s0 += o0.x; q0 += o0.y; s1 += o1.x; q1 += o1.y;
            }
            const float mu0 = s0 * (1.f / HH), rs0 = rsqrtf(q0 * (1.f / HH) - mu0 * mu0 + EPSF);
            const float mu1 = s1 * (1.f / HH), rs1 = rsqrtf(q1 * (1.f / HH) - mu1 * mu1 + EPSF);
#pragma unroll
            for (int j = 0; j < 8; ++j)
#pragma unroll
                for (int e = 0; e < 4; ++e) {
                    int col = cb + 8 * j + q2 + (e & 1);
                    int gcol = egq * HH + col;
                    float mu = (e < 2) ? mu0 : mu1, rs = (e < 2) ? rs0 : rs1;
                    size_t m = (e < 2) ? mA : mB;
                    g_a[m * GG + gcol] = (acc[j][e] - mu) * rs * gx[gcol] + bx[gcol] + bias[gcol];
                }
        }
    }
}

// ---------------- fused v3 (R13/R15-passing version, unchanged) ----------------
__device__ __forceinline__ void issue_whh(uint32_t sb, int tid, int gq, int buf) {
    const uint32_t base = sb + (buf ? F_B1 : F_B0);
#pragma unroll
    for (int it = 0; it < 16; ++it) {
        int c = tid + it * NTS;                 // 4096 transfers: hi then lo
        int part = c >> 11, cc = c & 2047;
        int n = cc >> 4, k8 = (cc & 15) * 8;
        const __nv_bfloat16* src = (part ? g_whh_lo : g_whh_hi) + (size_t)(gq * HH + n) * HH + k8;
        CPA16(base + part * 34816 + n * 272 + k8 * 2, src);
    }
    CP_COMMIT();
}

extern "C" __global__ void __launch_bounds__(NTS, 1)
fused_kernel(const float* __restrict__ gh, const float* __restrict__ bh,
             const float* __restrict__ gc, const float* __restrict__ bc,
             const float* __restrict__ h0, const float* __restrict__ c0,
             float* __restrict__ out, int write_hn)
{
    extern __shared__ char smc[];
    const uint32_t sb = smem_u32(smc);
    const int tid = threadIdx.x, lane = tid & 31, wid = tid >> 5;
    const int m0 = blockIdx.x * 64;
    const int wr0 = (wid >> 1) * 16;
    const int half = wid & 1, cb = half * 64;

    issue_whh(sb, tid, 0, 0);                   // B for (t=0, gate i) -> buf 0

#pragma unroll
    for (int it = 0; it < 8; ++it) {
        int c = tid + it * NTS;
        int row = c >> 5, c4 = (c & 31) * 4;
        float4 v = *(const float4*)(h0 + (size_t)(m0 + row) * HH + c4);
        __nv_bfloat16 b0 = __float2bfloat16(v.x), b1 = __float2bfloat16(v.y);
        __nv_bfloat16 b2 = __float2bfloat16(v.z), b3 = __float2bfloat16(v.w);
        uint2 hp, lp;
        hp.x = pack2(b0, b1); hp.y = pack2(b2, b3);
        lp.x = pack2(__float2bfloat16(v.x - __bfloat162float(b0)),
                     __float2bfloat16(v.y - __bfloat162float(b1)));
        lp.y = pack2(__float2bfloat16(v.z - __bfloat162float(b2)),
                     __float2bfloat16(v.w - __bfloat162float(b3)));
        *(uint2*)(smc + F_AHI + row * 272 + c4 * 2) = hp;
        *(uint2*)(smc + F_ALO + row * 272 + c4 * 2) = lp;
    }

    const int rA = wr0 + (lane >> 2), rB = rA + 8;
    const size_t bidxA = (size_t)m0 + rA, bidxB = bidxA + 8;
    const int q2 = 2 * (lane & 3);

    float C[8][4];
#pragma unroll
    for (int j = 0; j < 8; ++j) {
        float2 va = *(const float2*)(c0 + bidxA * HH + cb + 8 * j + q2);
        float2 vb = *(const float2*)(c0 + bidxB * HH + cb + 8 * j + q2);
        C[j][0] = va.x; C[j][1] = va.y; C[j][2] = vb.x; C[j][3] = vb.y;
    }

    const uint32_t abase = sb + F_AHI + (wr0 + (lane & 15)) * 272 + ((lane >> 4) << 4);
    const uint32_t bfo = ((cb + (lane & 7) + ((lane >> 4) << 3)) * 272 + (((lane >> 3) & 1) << 4));

    float accA[8][4], accB[8][4], S[8][4];
    float2 apA[8], apB[8];
    float sc0, qc0, sc1, qc1;

    auto mma_phase = [&](float (&ACC)[8][4], int buf) {
        const uint32_t bb = sb + (buf ? F_B1 : F_B0) + bfo;
#pragma unroll
        for (int j = 0; j < 8; ++j) { ACC[j][0] = ACC[j][1] = ACC[j][2] = ACC[j][3] = 0.f; }
#pragma unroll
        for (int ks = 0; ks < 8; ++ks) {
            uint32_t ah[4], al[4];
            ldsm4(ah, abase + ks * 32);
            ldsm4(al, abase + ks * 32 + (F_ALO - F_AHI));
#pragma unroll
            for (int g = 0; g < 4; ++g) {
                uint32_t bh4[4], bl4[4];
                uint32_t ba = bb + g * 16 * 272 + ks * 32;
                ldsm4(bh4, ba);
                ldsm4(bl4, ba + 34816);
                mma16816(ACC[2 * g],     ah, bh4[0], bh4[1]);
                mma16816(ACC[2 * g + 1], ah, bh4[2], bh4[3]);
                mma16816(ACC[2 * g],     al, bh4[0], bh4[1]);
                mma16816(ACC[2 * g + 1], al, bh4[2], bh4[3]);
                mma16816(ACC[2 * g],     ah, bl4[0], bl4[1]);
                mma16816(ACC[2 * g + 1], ah, bl4[2], bl4[3]);
            }
        }
    };

    auto load_ap = [&](int t, int gq) {
        const float* aA = g_a + ((size_t)bidxA * TT + t) * GG + gq * HH + cb;
        const float* aB = g_a + ((size_t)bidxB * TT + t) * GG + gq * HH + cb;
#pragma unroll
        for (int j = 0; j < 8; ++j) {
            apA[j] = *(const float2*)(aA + 8 * j + q2);
            apB[j] = *(const float2*)(aB + 8 * j + q2);
        }
    };

    auto gate_ln = [&](float (&ACC)[8][4], int reg,
                       float& mu0, float& rs0, float& mu1, float& rs1) {
        float2* red = (float2*)(smc + F_RED + reg * 1024);
        float s0 = 0.f, q0 = 0.f, s1 = 0.f, q1 = 0.f;
#pragma unroll
        for (int j = 0; j < 8; ++j) {
            s0 += ACC[j][0] + ACC[j][1]; q0 += ACC[j][0] * ACC[j][0] + ACC[j][1] * ACC[j][1];
            s1 += ACC[j][2] + ACC[j][3]; q1 += ACC[j][2] * ACC[j][2] + ACC[j][3] * ACC[j][3];
        }
        s0 = qsum(s0); q0 = qsum(q0); s1 = qsum(s1); q1 = qsum(q1);
        if ((lane & 3) == 0) {
            red[rA * 2 + half] = make_float2(s0, q0);
            red[rB * 2 + half] = make_float2(s1, q1);
        }
        __syncthreads();
        float2 o0 = red[rA * 2 + (1 - half)], o1 = red[rB * 2 + (1 - half)];
        s0 += o0.x; q0 += o0.y; s1 += o1.x; q1 += o1.y;
        mu0 = s0 * (1.f / HH); rs0 = rsqrtf(q0 * (1.f / HH) - mu0 * mu0 + EPSF);
        mu1 = s1 * (1.f / HH); rs1 = rsqrtf(q1 * (1.f / HH) - mu1 * mu1 + EPSF);
    };

    auto epi = [&](float (&ACC)[8][4], int gq, int reg, int mode) {
        float mu0, rs0, mu1, rs1;
        gate_ln(ACC, reg, mu0, rs0, mu1, rs1);
#pragma unroll
        for (int j = 0; j < 8; ++j) {
            int colb = cb + 8 * j + q2;
            float2 gh2 = *(const float2*)(gh + gq * HH + colb);
            float2 bh2 = *(const float2*)(bh + gq * HH + colb);
            float ar[4] = {apA[j].x, apA[j].y, apB[j].x, apB[j].y};
#pragma unroll
            for (int e = 0; e < 4; ++e) {
                float mu = (e < 2) ? mu0 : mu1, rs = (e < 2) ? rs0 : rs1;
                float gv = (e & 1) ? gh2.y : gh2.x;
                float bv = (e & 1) ? bh2.y : bh2.x;
                float gn = (ACC[j][e] - mu) * rs * gv + bv + ar[e];
                if (mode == 0) {
                    S[j][e] = sigm(gn);
                } else if (mode == 1) {
                    S[j][e] *= tanh_fast(gn);
                } else if (mode == 2) {
                    float cv = sigm(gn) * C[j][e] + S[j][e];
                    C[j][e] = cv;
                    if (e < 2) { sc0 += cv; qc0 += cv * cv; }
                    else       { sc1 += cv; qc1 += cv * cv; }
                } else {
                    ACC[j][e] = sigm(gn);
                }
            }
        }
    };

#pragma unroll 1
    for (int t = 0; t < TT; ++t) {
        sc0 = 0.f; qc0 = 0.f; sc1 = 0.f; qc1 = 0.f;

        CP_WAIT0(); __syncthreads();
        issue_whh(sb, tid, 2, (t * 4 + 1) & 1);
        mma_phase(accA, (t * 4) & 1);
        load_ap(t, 0);

        CP_WAIT0(); __syncthreads();
        issue_whh(sb, tid, 1, (t * 4 + 2) & 1);
        mma_phase(accB, (t * 4 + 1) & 1);
        epi(accA, 0, 0, 0);
        load_ap(t, 2);

        CP_WAIT0(); __syncthreads();
        issue_whh(sb, tid, 3, (t * 4 + 3) & 1);
        mma_phase(accA, (t * 4 + 2) & 1);
        epi(accB, 2, 1, 1);
        load_ap(t, 1);

        CP_WAIT0(); __syncthreads();
        if (t + 1 < TT) issue_whh(sb, tid, 0, (t * 4 + 4) & 1);
        mma_phase(accB, (t * 4 + 3) & 1);
        epi(accA, 1, 0, 2);
        load_ap(t, 3);

        epi(accB, 3, 1, 3);

        {
            float2* red = (float2*)(smc + F_RED);
            float s0 = qsum(sc0), q0 = qsum(qc0), s1 = qsum(sc1), q1 = qsum(qc1);
            if ((lane & 3) == 0) {
                red[rA * 2 + half] = make_float2(s0, q0);
                red[rB * 2 + half] = make_float2(s1, q1);
            }
            __syncthreads();
            float2 o0 = red[rA * 2 + (1 - half)], o1 = red[rB * 2 + (1 - half)];
            s0 += o0.x; q0 += o0.y; s1 += o1.x; q1 += o1.y;
            const float mc0 = s0 * (1.f / HH), rc0 = rsqrtf(q0 * (1.f / HH) - mc0 * mc0 + EPSF);
            const float mc1 = s1 * (1.f / HH), rc1 = rsqrtf(q1 * (1.f / HH) - mc1 * mc1 + EPSF);

            float* oA = out + (bidxA * TT + t) * HH;
            float* oB = out + (bidxB * TT + t) * HH;
#pragma unroll
            for (int j = 0; j < 8; ++j) {
                int colb = cb + 8 * j + q2;
                float2 gc2 = *(const float2*)(gc + colb);
                float2 bc2 = *(const float2*)(bc + colb);
                float hv[4];
#pragma unroll
                for (int e = 0; e < 4; ++e) {
                    float mc = (e < 2) ? mc0 : mc1, rc = (e < 2) ? rc0 : rc1;
                    float gv = (e & 1) ? gc2.y : gc2.x;
                    float bv = (e & 1) ? bc2.y : bc2.x;
                    float cl = (C[j][e] - mc) * rc * gv + bv;
                    hv[e] = accB[j][e] * tanh_fast(cl);
                }
                *(float2*)(oA + colb) = make_float2(hv[0], hv[1]);
                *(float2*)(oB + colb) = make_float2(hv[2], hv[3]);
                if (write_hn && t == TT - 1) {
                    *(float2*)(out + (size_t)BB * TT * HH + bidxA * HH + colb) = make_float2(hv[0], hv[1]);
                    *(float2*)(out + (size_t)BB * TT * HH + bidxB * HH + colb) = make_float2(hv[2], hv[3]);
                }
                __nv_bfloat16 b0 = __float2bfloat16(hv[0]), b1 = __float2bfloat16(hv[1]);
                __nv_bfloat16 b2 = __float2bfloat16(hv[2]), b3 = __float2bfloat16(hv[3]);
                *(uint32_t*)(smc + F_AHI + rA * 272 + colb * 2) = pack2(b0, b1);
                *(uint32_t*)(smc + F_AHI + rB * 272 + colb * 2) = pack2(b2, b3);
                *(uint32_t*)(smc + F_ALO + rA * 272 + colb * 2) =
                    pack2(__float2bfloat16(hv[0] - __bfloat162float(b0)),
                          __float2bfloat16(hv[1] - __bfloat162float(b1)));
                *(uint32_t*)(smc + F_ALO + rB * 272 + colb * 2) =
                    pack2(__float2bfloat16(hv[2] - __bfloat162float(b2)),
                          __float2bfloat16(hv[3] - __bfloat162float(b3)));
            }
        }
    }
}

// ---------------- host ----------------
extern "C" void kernel_launch(void* const* d_in, const int* in_sizes, int n_in,
                              void* d_out, int out_size)
{
    const float* x    = (const float*)d_in[0];
    const float* h0   = (const float*)d_in[1];
    const float* c0   = (const float*)d_in[2];
    const float* W_ih = (const float*)d_in[3];
    const float* W_hh = (const float*)d_in[4];
    const float* bias = (const float*)d_in[5];
    const float* g_x  = (const float*)d_in[6];
    const float* b_x  = (const float*)d_in[7];
    const float* gh   = (const float*)d_in[8];
    const float* bh   = (const float*)d_in[9];
    const float* gc   = (const float*)d_in[10];
    const float* bc   = (const float*)d_in[11];
    float* out = (float*)d_out;

    cudaFuncSetAttribute(proj_kernel,  cudaFuncAttributeMaxDynamicSharedMemorySize, SMEM_PROJ);
    cudaFuncSetAttribute(fused_kernel, cudaFuncAttributeMaxDynamicSharedMemorySize, SMEM_FUSED);

    split_wih<<<(GG * II + 255) / 256, 256>>>(W_ih);
    split_whh<<<(GG * HH + 255) / 256, 256>>>(W_hh);

    proj_kernel<<<(BB * TT) / 64, NTH, SMEM_PROJ>>>(x, bias, g_x, b_x);

    const long long need = (long long)BB * TT * HH + (long long)BB * HH;
    const int write_full = (out_size >= need) ? 1 : 0;

    fused_kernel<<<BB / 64, NTS, SMEM_FUSED>>>(gh, bh, gc, bc, h0, c0, out, write_full);
}